// round 6
// baseline (speedup 1.0000x reference)
#include <cuda_runtime.h>
#include <cuda_bf16.h>
#include <math.h>
#include <stdint.h>

#define NN 50000
#define EE 800000
#define NB 49  // ceil(NN/1024)

// ---------------- device scratch (no allocations allowed) ----------------
__device__ int   g_is64;
__device__ int   g_cnt[NN];
__device__ int   g_off[NN];
__device__ int   g_cur[NN];
__device__ int   g_csr[EE];
__device__ int   g_bsum[NB];
__device__ int   g_bbase[NB];
__device__ __align__(16) __nv_bfloat16 g_B1b[256 * 128];  // B_ex[n][k] = W[k][n], [Wl|Wr]
__device__ __align__(16) __nv_bfloat16 g_B2b[256 * 128];
__device__ __align__(16) __nv_bfloat16 g_h1b[NN * 128];
__device__ float g_C[NN * 256];   // cols 0:128 = h@W_l (to aggregate), 128:256 = h@W_r
__device__ float g_a[NN];
__device__ float g_c[NN];

__device__ __forceinline__ int edge_at(const void* ei, long i) {
    return g_is64 ? (int)((const long long*)ei)[i] : ((const int*)ei)[i];
}

__device__ __forceinline__ uint32_t smem_u32(const void* p) {
    uint32_t a;
    asm("{ .reg .u64 t; cvta.to.shared.u64 t, %1; cvt.u32.u64 %0, t; }" : "=r"(a) : "l"(p));
    return a;
}

// ---------------- prep: detect int width + zero counts + pack weights ----------------
#define ZB ((NN + 255) / 256)            // 196 blocks zero g_cnt
#define PB ((256 * 128 + 255) / 256)     // 128 blocks pack weights
__global__ void k_prep(const void* ei,
                       const float* __restrict__ Wl1, const float* __restrict__ Wr1,
                       const float* __restrict__ Wl2, const float* __restrict__ Wr2) {
    int b = blockIdx.x;
    if (b == 0 && threadIdx.x == 0) {
        const int* w = (const int*)ei;
        int all0 = 1;
#pragma unroll
        for (int i = 0; i < 64; i++) all0 &= (w[2 * i + 1] == 0);
        g_is64 = all0;
    }
    if (b < ZB) {
        int i = b * 256 + threadIdx.x;
        if (i < NN) g_cnt[i] = 0;
    } else {
        int i = (b - ZB) * 256 + threadIdx.x;
        if (i < 256 * 128) {
            int n = i >> 7, k = i & 127;
            float v1 = (n < 128) ? Wl1[k * 128 + n] : Wr1[k * 128 + (n - 128)];
            float v2 = (n < 128) ? Wl2[k * 128 + n] : Wr2[k * 128 + (n - 128)];
            g_B1b[i] = __float2bfloat16(v1);
            g_B2b[i] = __float2bfloat16(v2);
        }
    }
}

__global__ void k_count(const void* ei) {
    int e = blockIdx.x * blockDim.x + threadIdx.x;
    if (e >= EE) return;
    int t = edge_at(ei, (long)EE + e);
    atomicAdd(&g_cnt[t], 1);
}

// hierarchical exclusive scan of g_cnt -> g_off (coalesced)
__global__ void k_scan1() {
    __shared__ int ws[32];
    int tid = threadIdx.x, lane = tid & 31, w = tid >> 5;
    int i = blockIdx.x * 1024 + tid;
    int v = (i < NN) ? g_cnt[i] : 0;
    int x = v;
#pragma unroll
    for (int d = 1; d < 32; d <<= 1) { int t = __shfl_up_sync(~0u, x, d); if (lane >= d) x += t; }
    if (lane == 31) ws[w] = x;
    __syncthreads();
    if (w == 0) {
        int y = ws[lane];
#pragma unroll
        for (int d = 1; d < 32; d <<= 1) { int t = __shfl_up_sync(~0u, y, d); if (lane >= d) y += t; }
        ws[lane] = y;
    }
    __syncthreads();
    int base = w ? ws[w - 1] : 0;
    int incl = base + x;
    if (i < NN) g_off[i] = incl - v;
    if (tid == 1023) g_bsum[blockIdx.x] = incl;
}

__global__ void k_scan2() {
    __shared__ int s0;
    int tid = threadIdx.x, lane = tid & 31, w = tid >> 5;
    int v = (tid < NB) ? g_bsum[tid] : 0;
    int x = v;
#pragma unroll
    for (int d = 1; d < 32; d <<= 1) { int t = __shfl_up_sync(~0u, x, d); if (lane >= d) x += t; }
    if (w == 0 && lane == 31) s0 = x;
    __syncthreads();
    int excl = x - v + (w ? s0 : 0);
    if (tid < NB) g_bbase[tid] = excl;
}

__global__ void k_scan3() {
    int i = blockIdx.x * 1024 + threadIdx.x;
    if (i < NN) {
        int o = g_off[i] + g_bbase[blockIdx.x];
        g_off[i] = o;
        g_cur[i] = o;
    }
}

__global__ void k_scatter(const void* ei) {
    int e = blockIdx.x * blockDim.x + threadIdx.x;
    if (e >= EE) return;
    int s = edge_at(ei, e);
    int t = edge_at(ei, (long)EE + e);
    int pos = atomicAdd(&g_cur[t], 1);
    g_csr[pos] = s;
}

// ---------------- HMMA bf16 GEMM: C tile[128,128] = A[128,128] @ B_ex[colrange]^T ----------------
// mma.sync.aligned.m16n8k16; 256 thr = 8 warps (2M x 4N), warp tile 64x32, K=128 in smem.
#define ASTRIDE 136

__global__ __launch_bounds__(256) void k_gemm_mma(const float* __restrict__ x, int layer, int M) {
    extern __shared__ __nv_bfloat16 sm[];
    __nv_bfloat16* As = sm;
    __nv_bfloat16* Bs = sm + 128 * ASTRIDE;

    const int tid = threadIdx.x;
    const int lane = tid & 31, w = tid >> 5;
    const int rowBase = blockIdx.x * 128;
    const int colBase = blockIdx.y * 128;

    {
        const __nv_bfloat16* Bsrc = (layer ? g_B2b : g_B1b) + (size_t)colBase * 128;
        int r = tid >> 1, half = tid & 1;
        const uint4* src = (const uint4*)(Bsrc + r * 128 + half * 64);
        uint4* dst = (uint4*)(Bs + r * ASTRIDE + half * 64);
#pragma unroll
        for (int i = 0; i < 8; i++) dst[i] = src[i];
    }
    {
        int r = tid >> 1, half = tid & 1;
        int grow = rowBase + r;
        if (layer == 0) {
            const float4* src = (const float4*)(x + (size_t)grow * 128 + half * 64);
            uint32_t* dst = (uint32_t*)(As + r * ASTRIDE + half * 64);
#pragma unroll
            for (int i = 0; i < 16; i++) {
                float4 v = make_float4(0.f, 0.f, 0.f, 0.f);
                if (grow < M) v = src[i];
                __nv_bfloat162 lo = __floats2bfloat162_rn(v.x, v.y);
                __nv_bfloat162 hi = __floats2bfloat162_rn(v.z, v.w);
                dst[i * 2]     = *(uint32_t*)&lo;
                dst[i * 2 + 1] = *(uint32_t*)&hi;
            }
        } else {
            const uint4* src = (const uint4*)(g_h1b + (size_t)grow * 128 + half * 64);
            uint4* dst = (uint4*)(As + r * ASTRIDE + half * 64);
            uint4 z = make_uint4(0u, 0u, 0u, 0u);
#pragma unroll
            for (int i = 0; i < 8; i++) dst[i] = (grow < M) ? src[i] : z;
        }
    }
    __syncthreads();

    const int wm = w >> 2;
    const int wn = w & 3;

    float acc[4][4][4];
#pragma unroll
    for (int i = 0; i < 4; i++)
#pragma unroll
        for (int j = 0; j < 4; j++)
#pragma unroll
            for (int q = 0; q < 4; q++) acc[i][j][q] = 0.f;

#pragma unroll
    for (int ks = 0; ks < 8; ks++) {
        const int k0 = ks * 16;
        uint32_t a[4][4];
#pragma unroll
        for (int mf = 0; mf < 4; mf++) {
            uint32_t addr = smem_u32(As + (wm * 64 + mf * 16 + (lane & 15)) * ASTRIDE + k0 + (lane >> 4) * 8);
            asm volatile("ldmatrix.sync.aligned.m8n8.x4.shared.b16 {%0,%1,%2,%3}, [%4];"
                         : "=r"(a[mf][0]), "=r"(a[mf][1]), "=r"(a[mf][2]), "=r"(a[mf][3]) : "r"(addr));
        }
        uint32_t b[4][2];
#pragma unroll
        for (int nh = 0; nh < 2; nh++) {
            uint32_t r0, r1, r2, r3;
            uint32_t addr = smem_u32(Bs + (wn * 32 + nh * 16 + (lane & 15)) * ASTRIDE + k0 + (lane >> 4) * 8);
            asm volatile("ldmatrix.sync.aligned.m8n8.x4.shared.b16 {%0,%1,%2,%3}, [%4];"
                         : "=r"(r0), "=r"(r1), "=r"(r2), "=r"(r3) : "r"(addr));
            b[nh * 2 + 0][0] = r0; b[nh * 2 + 0][1] = r2;
            b[nh * 2 + 1][0] = r1; b[nh * 2 + 1][1] = r3;
        }
#pragma unroll
        for (int mf = 0; mf < 4; mf++)
#pragma unroll
            for (int nf = 0; nf < 4; nf++) {
                asm volatile(
                    "mma.sync.aligned.m16n8k16.row.col.f32.bf16.bf16.f32 "
                    "{%0,%1,%2,%3}, {%4,%5,%6,%7}, {%8,%9}, {%0,%1,%2,%3};"
                    : "+f"(acc[mf][nf][0]), "+f"(acc[mf][nf][1]), "+f"(acc[mf][nf][2]), "+f"(acc[mf][nf][3])
                    : "r"(a[mf][0]), "r"(a[mf][1]), "r"(a[mf][2]), "r"(a[mf][3]),
                      "r"(b[nf][0]), "r"(b[nf][1]));
            }
    }

#pragma unroll
    for (int mf = 0; mf < 4; mf++) {
        int r0 = rowBase + wm * 64 + mf * 16 + (lane >> 2);
#pragma unroll
        for (int nf = 0; nf < 4; nf++) {
            int col = colBase + wn * 32 + nf * 8 + (lane & 3) * 2;
            if (r0 < M) {
                float2* p = (float2*)(g_C + (size_t)r0 * 256 + col);
                *p = make_float2(acc[mf][nf][0], acc[mf][nf][1]);
            }
            if (r0 + 8 < M) {
                float2* p = (float2*)(g_C + (size_t)(r0 + 8) * 256 + col);
                *p = make_float2(acc[mf][nf][2], acc[mf][nf][3]);
            }
        }
    }
}

// ---------------- layer 1 epilogue: CSR mean-aggregate + bias + relu -> bf16 h1 ----------------
__global__ void k_epi1(const float* __restrict__ bl) {
    int gw = (blockIdx.x * blockDim.x + threadIdx.x) >> 5;
    int lane = threadIdx.x & 31;
    if (gw >= NN) return;
    int s = g_off[gw], cnt = g_cnt[gw];
    float4 a0 = make_float4(0.f, 0.f, 0.f, 0.f);
    float4 a1 = make_float4(0.f, 0.f, 0.f, 0.f);
    float4 a2 = make_float4(0.f, 0.f, 0.f, 0.f);
    float4 a3 = make_float4(0.f, 0.f, 0.f, 0.f);
    int e = 0;
    for (; e + 4 <= cnt; e += 4) {
        int j0 = g_csr[s + e], j1 = g_csr[s + e + 1], j2 = g_csr[s + e + 2], j3 = g_csr[s + e + 3];
        float4 v0 = *(const float4*)&g_C[(size_t)j0 * 256 + lane * 4];
        float4 v1 = *(const float4*)&g_C[(size_t)j1 * 256 + lane * 4];
        float4 v2 = *(const float4*)&g_C[(size_t)j2 * 256 + lane * 4];
        float4 v3 = *(const float4*)&g_C[(size_t)j3 * 256 + lane * 4];
        a0.x += v0.x; a0.y += v0.y; a0.z += v0.z; a0.w += v0.w;
        a1.x += v1.x; a1.y += v1.y; a1.z += v1.z; a1.w += v1.w;
        a2.x += v2.x; a2.y += v2.y; a2.z += v2.z; a2.w += v2.w;
        a3.x += v3.x; a3.y += v3.y; a3.z += v3.z; a3.w += v3.w;
    }
    for (; e < cnt; e++) {
        int j = g_csr[s + e];
        float4 v = *(const float4*)&g_C[(size_t)j * 256 + lane * 4];
        a0.x += v.x; a0.y += v.y; a0.z += v.z; a0.w += v.w;
    }
    float inv = 1.0f / (float)max(cnt, 1);
    float4 r = *(const float4*)&g_C[(size_t)gw * 256 + 128 + lane * 4];
    float4 bb = *(const float4*)&bl[lane * 4];
    float ox = fmaxf((a0.x + a1.x + a2.x + a3.x) * inv + r.x + bb.x, 0.f);
    float oy = fmaxf((a0.y + a1.y + a2.y + a3.y) * inv + r.y + bb.y, 0.f);
    float oz = fmaxf((a0.z + a1.z + a2.z + a3.z) * inv + r.z + bb.z, 0.f);
    float ow = fmaxf((a0.w + a1.w + a2.w + a3.w) * inv + r.w + bb.w, 0.f);
    __nv_bfloat162 p0 = __floats2bfloat162_rn(ox, oy);
    __nv_bfloat162 p1 = __floats2bfloat162_rn(oz, ow);
    uint64_t pk = ((uint64_t)(*(uint32_t*)&p1) << 32) | (uint64_t)(*(uint32_t*)&p0);
    *(uint64_t*)(g_h1b + (size_t)gw * 128 + lane * 4) = pk;
}

// ---------------- layer 2 epilogue: aggregate + bias fused with W_e dots ----------------
__global__ void k_epi2(const float* __restrict__ bl, const float* __restrict__ We) {
    int gw = (blockIdx.x * blockDim.x + threadIdx.x) >> 5;
    int lane = threadIdx.x & 31;
    if (gw >= NN) return;
    int s = g_off[gw], cnt = g_cnt[gw];
    float4 a0 = make_float4(0.f, 0.f, 0.f, 0.f);
    float4 a1 = make_float4(0.f, 0.f, 0.f, 0.f);
    float4 a2 = make_float4(0.f, 0.f, 0.f, 0.f);
    float4 a3 = make_float4(0.f, 0.f, 0.f, 0.f);
    int e = 0;
    for (; e + 4 <= cnt; e += 4) {
        int j0 = g_csr[s + e], j1 = g_csr[s + e + 1], j2 = g_csr[s + e + 2], j3 = g_csr[s + e + 3];
        float4 v0 = *(const float4*)&g_C[(size_t)j0 * 256 + lane * 4];
        float4 v1 = *(const float4*)&g_C[(size_t)j1 * 256 + lane * 4];
        float4 v2 = *(const float4*)&g_C[(size_t)j2 * 256 + lane * 4];
        float4 v3 = *(const float4*)&g_C[(size_t)j3 * 256 + lane * 4];
        a0.x += v0.x; a0.y += v0.y; a0.z += v0.z; a0.w += v0.w;
        a1.x += v1.x; a1.y += v1.y; a1.z += v1.z; a1.w += v1.w;
        a2.x += v2.x; a2.y += v2.y; a2.z += v2.z; a2.w += v2.w;
        a3.x += v3.x; a3.y += v3.y; a3.z += v3.z; a3.w += v3.w;
    }
    for (; e < cnt; e++) {
        int j = g_csr[s + e];
        float4 v = *(const float4*)&g_C[(size_t)j * 256 + lane * 4];
        a0.x += v.x; a0.y += v.y; a0.z += v.z; a0.w += v.w;
    }
    float inv = 1.0f / (float)max(cnt, 1);
    float4 r = *(const float4*)&g_C[(size_t)gw * 256 + 128 + lane * 4];
    float4 bb = *(const float4*)&bl[lane * 4];
    float hx = (a0.x + a1.x + a2.x + a3.x) * inv + r.x + bb.x;
    float hy = (a0.y + a1.y + a2.y + a3.y) * inv + r.y + bb.y;
    float hz = (a0.z + a1.z + a2.z + a3.z) * inv + r.z + bb.z;
    float hw = (a0.w + a1.w + a2.w + a3.w) * inv + r.w + bb.w;
    float4 w0 = *(const float4*)&We[lane * 4];
    float4 w1 = *(const float4*)&We[128 + lane * 4];
    float pa = hx * w0.x + hy * w0.y + hz * w0.z + hw * w0.w;
    float pc = hx * w1.x + hy * w1.y + hz * w1.z + hw * w1.w;
#pragma unroll
    for (int d = 16; d > 0; d >>= 1) {
        pa += __shfl_xor_sync(0xffffffffu, pa, d);
        pc += __shfl_xor_sync(0xffffffffu, pc, d);
    }
    if (lane == 0) {
        g_a[gw] = pa;
        g_c[gw] = pc;
    }
}

// ---------------- edge scoring ----------------
__global__ void k_edge(const void* ei, const float* __restrict__ be, float* __restrict__ out) {
    int e = blockIdx.x * blockDim.x + threadIdx.x;
    if (e >= EE) return;
    int s = edge_at(ei, e);
    int t = edge_at(ei, (long)EE + e);
    float z = g_a[s] + g_c[t] + be[0];
    out[e] = 1.f / (1.f + __expf(-z));
}

// ---------------- launcher ----------------
extern "C" void kernel_launch(void* const* d_in, const int* in_sizes, int n_in,
                              void* d_out, int out_size) {
    const float* x   = (const float*)d_in[0];
    const void*  ei  = d_in[1];
    const float* Wl1 = (const float*)d_in[2];
    const float* bl1 = (const float*)d_in[3];
    const float* Wr1 = (const float*)d_in[4];
    const float* Wl2 = (const float*)d_in[5];
    const float* bl2 = (const float*)d_in[6];
    const float* Wr2 = (const float*)d_in[7];
    const float* We  = (const float*)d_in[8];
    const float* be  = (const float*)d_in[9];
    float* out = (float*)d_out;

    const int smemBytes = 2 * 128 * ASTRIDE * (int)sizeof(__nv_bfloat16);
    cudaFuncSetAttribute(k_gemm_mma, cudaFuncAttributeMaxDynamicSharedMemorySize, smemBytes);

    k_prep<<<ZB + PB, 256>>>(ei, Wl1, Wr1, Wl2, Wr2);
    k_count<<<(EE + 255) / 256, 256>>>(ei);
    k_scan1<<<NB, 1024>>>();
    k_scan2<<<1, 64>>>();
    k_scan3<<<NB, 1024>>>();
    k_scatter<<<(EE + 255) / 256, 256>>>(ei);

    dim3 gg((NN + 127) / 128, 2);
    const int epiBlocks = (NN * 32 + 255) / 256;

    k_gemm_mma<<<gg, 256, smemBytes>>>(x, 0, NN);
    k_epi1<<<epiBlocks, 256>>>(bl1);
    k_gemm_mma<<<gg, 256, smemBytes>>>(x, 1, NN);
    k_epi2<<<epiBlocks, 256>>>(bl2, We);
    k_edge<<<(EE + 255) / 256, 256>>>(ei, be, out);
}

// round 7
// speedup vs baseline: 1.5974x; 1.5974x over previous
#include <cuda_runtime.h>
#include <cuda_bf16.h>
#include <math.h>
#include <stdint.h>

#define NN 50000
#define EE 800000
#define NB 49  // ceil(NN/1024)

// ---------------- device scratch (no allocations allowed) ----------------
__device__ int   g_is64;
__device__ int   g_cnt[NN];
__device__ int   g_off[NN];
__device__ int   g_cur[NN];
__device__ int   g_csr[EE];
__device__ __align__(16) __nv_bfloat16 g_B1b[256 * 128];  // B_ex[n][k] = W1[k][n], [Wl1|Wr1]
__device__ __align__(16) __nv_bfloat16 g_Cl[NN * 128];    // x@Wl1 bf16 (gathered per edge)
__device__ float g_Cr[NN * 128];                          // x@Wr1 fp32 (read once per node)
__device__ __align__(16) float g_w2[4 * 128];  // [Wl2@We0 | Wl2@We1 | Wr2@We0 | Wr2@We1]
__device__ float g_w2c[2];                     // b2.We0, b2.We1
__device__ float2 g_uv[NN];   // per-node (u,v): aggregated-over-neighbors scalars
__device__ float2 g_pq[NN];   // per-node (p,q): self scalars
__device__ float g_a[NN];
__device__ float g_c[NN];

__device__ __forceinline__ int edge_at(const void* ei, long i) {
    return g_is64 ? (int)((const long long*)ei)[i] : ((const int*)ei)[i];
}

__device__ __forceinline__ uint32_t smem_u32(const void* p) {
    uint32_t a;
    asm("{ .reg .u64 t; cvta.to.shared.u64 t, %1; cvt.u32.u64 %0, t; }" : "=r"(a) : "l"(p));
    return a;
}

__device__ __forceinline__ void acc_bf16x4(float4& a, uint64_t pk) {
    uint32_t lo = (uint32_t)pk, hi = (uint32_t)(pk >> 32);
    float2 f0 = __bfloat1622float2(*(__nv_bfloat162*)&lo);
    float2 f1 = __bfloat1622float2(*(__nv_bfloat162*)&hi);
    a.x += f0.x; a.y += f0.y; a.z += f1.x; a.w += f1.y;
}

// ---------------- prep: detect + zero cnt + pack W1 (bf16) + fold layer2 weights ----------------
#define ZB ((NN + 255) / 256)          // 196 blocks: zero g_cnt
#define PBB ((256 * 128 + 255) / 256)  // 128 blocks: pack B1
#define WB 3                           // 3 blocks: w2 folds (514 dots of length 128)
__global__ void k_prep(const void* ei,
                       const float* __restrict__ Wl1, const float* __restrict__ Wr1,
                       const float* __restrict__ Wl2, const float* __restrict__ Wr2,
                       const float* __restrict__ bl2, const float* __restrict__ We) {
    int b = blockIdx.x;
    if (b == 0 && threadIdx.x == 0) {
        const int* w = (const int*)ei;
        int all0 = 1;
#pragma unroll
        for (int i = 0; i < 64; i++) all0 &= (w[2 * i + 1] == 0);
        g_is64 = all0;
    }
    if (b < ZB) {
        int i = b * 256 + threadIdx.x;
        if (i < NN) g_cnt[i] = 0;
    } else if (b < ZB + PBB) {
        int i = (b - ZB) * 256 + threadIdx.x;
        int n = i >> 7, k = i & 127;
        float v = (n < 128) ? Wl1[k * 128 + n] : Wr1[k * 128 + (n - 128)];
        g_B1b[i] = __float2bfloat16(v);
    } else {
        int t = (b - ZB - PBB) * 256 + threadIdx.x;  // 0..767
        if (t < 512) {
            int vec = t >> 7;   // 0: Wl2.We0  1: Wl2.We1  2: Wr2.We0  3: Wr2.We1
            int m = t & 127;
            const float* W = (vec < 2) ? Wl2 : Wr2;
            const float* we = We + ((vec & 1) ? 128 : 0);
            float s = 0.f;
#pragma unroll 8
            for (int k = 0; k < 128; k++) s += W[m * 128 + k] * we[k];
            g_w2[vec * 128 + m] = s;
        } else if (t < 514) {
            const float* we = We + ((t - 512) ? 128 : 0);
            float s = 0.f;
#pragma unroll 8
            for (int k = 0; k < 128; k++) s += bl2[k] * we[k];
            g_w2c[t - 512] = s;
        }
    }
}

__global__ void k_count(const void* ei) {
    int e = blockIdx.x * blockDim.x + threadIdx.x;
    if (e >= EE) return;
    int t = edge_at(ei, (long)EE + e);
    atomicAdd(&g_cnt[t], 1);
}

// ---------------- single-kernel coalesced exclusive scan (1 block, 49 chunks) ----------------
__global__ void k_scan_all() {
    __shared__ int ws[32];
    __shared__ int carry;
    int tid = threadIdx.x, lane = tid & 31, w = tid >> 5;
    if (tid == 0) carry = 0;
    __syncthreads();
    for (int it = 0; it < NB; it++) {
        int i = it * 1024 + tid;
        int v = (i < NN) ? g_cnt[i] : 0;
        int x = v;
#pragma unroll
        for (int d = 1; d < 32; d <<= 1) { int t = __shfl_up_sync(~0u, x, d); if (lane >= d) x += t; }
        if (lane == 31) ws[w] = x;
        __syncthreads();
        if (w == 0) {
            int y = ws[lane];
#pragma unroll
            for (int d = 1; d < 32; d <<= 1) { int t = __shfl_up_sync(~0u, y, d); if (lane >= d) y += t; }
            ws[lane] = y;
        }
        __syncthreads();
        int base = (w ? ws[w - 1] : 0) + carry;
        int excl = base + x - v;
        if (i < NN) { g_off[i] = excl; g_cur[i] = excl; }
        __syncthreads();
        if (tid == 1023) carry = base + x;
        __syncthreads();
    }
}

__global__ void k_scatter(const void* ei) {
    int e = blockIdx.x * blockDim.x + threadIdx.x;
    if (e >= EE) return;
    int s = edge_at(ei, e);
    int t = edge_at(ei, (long)EE + e);
    int pos = atomicAdd(&g_cur[t], 1);
    g_csr[pos] = s;
}

// ---------------- HMMA bf16 GEMM (layer 1 only): tile[128,128] = x[128,128] @ B1^T ----------------
// y==0 -> x@Wl1 -> bf16 g_Cl ; y==1 -> x@Wr1 -> fp32 g_Cr
#define ASTRIDE 136

__global__ __launch_bounds__(256) void k_gemm_mma(const float* __restrict__ x, int M) {
    extern __shared__ __nv_bfloat16 sm[];
    __nv_bfloat16* As = sm;
    __nv_bfloat16* Bs = sm + 128 * ASTRIDE;

    const int tid = threadIdx.x;
    const int lane = tid & 31, w = tid >> 5;
    const int rowBase = blockIdx.x * 128;
    const int colBase = blockIdx.y * 128;

    {
        const __nv_bfloat16* Bsrc = g_B1b + (size_t)colBase * 128;
        int r = tid >> 1, half = tid & 1;
        const uint4* src = (const uint4*)(Bsrc + r * 128 + half * 64);
        uint4* dst = (uint4*)(Bs + r * ASTRIDE + half * 64);
#pragma unroll
        for (int i = 0; i < 8; i++) dst[i] = src[i];
    }
    {
        int r = tid >> 1, half = tid & 1;
        int grow = rowBase + r;
        const float4* src = (const float4*)(x + (size_t)grow * 128 + half * 64);
        uint32_t* dst = (uint32_t*)(As + r * ASTRIDE + half * 64);
#pragma unroll
        for (int i = 0; i < 16; i++) {
            float4 v = make_float4(0.f, 0.f, 0.f, 0.f);
            if (grow < M) v = src[i];
            __nv_bfloat162 lo = __floats2bfloat162_rn(v.x, v.y);
            __nv_bfloat162 hi = __floats2bfloat162_rn(v.z, v.w);
            dst[i * 2]     = *(uint32_t*)&lo;
            dst[i * 2 + 1] = *(uint32_t*)&hi;
        }
    }
    __syncthreads();

    const int wm = w >> 2;
    const int wn = w & 3;

    float acc[4][4][4];
#pragma unroll
    for (int i = 0; i < 4; i++)
#pragma unroll
        for (int j = 0; j < 4; j++)
#pragma unroll
            for (int q = 0; q < 4; q++) acc[i][j][q] = 0.f;

#pragma unroll
    for (int ks = 0; ks < 8; ks++) {
        const int k0 = ks * 16;
        uint32_t a[4][4];
#pragma unroll
        for (int mf = 0; mf < 4; mf++) {
            uint32_t addr = smem_u32(As + (wm * 64 + mf * 16 + (lane & 15)) * ASTRIDE + k0 + (lane >> 4) * 8);
            asm volatile("ldmatrix.sync.aligned.m8n8.x4.shared.b16 {%0,%1,%2,%3}, [%4];"
                         : "=r"(a[mf][0]), "=r"(a[mf][1]), "=r"(a[mf][2]), "=r"(a[mf][3]) : "r"(addr));
        }
        uint32_t b[4][2];
#pragma unroll
        for (int nh = 0; nh < 2; nh++) {
            uint32_t r0, r1, r2, r3;
            uint32_t addr = smem_u32(Bs + (wn * 32 + nh * 16 + (lane & 15)) * ASTRIDE + k0 + (lane >> 4) * 8);
            asm volatile("ldmatrix.sync.aligned.m8n8.x4.shared.b16 {%0,%1,%2,%3}, [%4];"
                         : "=r"(r0), "=r"(r1), "=r"(r2), "=r"(r3) : "r"(addr));
            b[nh * 2 + 0][0] = r0; b[nh * 2 + 0][1] = r2;
            b[nh * 2 + 1][0] = r1; b[nh * 2 + 1][1] = r3;
        }
#pragma unroll
        for (int mf = 0; mf < 4; mf++)
#pragma unroll
            for (int nf = 0; nf < 4; nf++) {
                asm volatile(
                    "mma.sync.aligned.m16n8k16.row.col.f32.bf16.bf16.f32 "
                    "{%0,%1,%2,%3}, {%4,%5,%6,%7}, {%8,%9}, {%0,%1,%2,%3};"
                    : "+f"(acc[mf][nf][0]), "+f"(acc[mf][nf][1]), "+f"(acc[mf][nf][2]), "+f"(acc[mf][nf][3])
                    : "r"(a[mf][0]), "r"(a[mf][1]), "r"(a[mf][2]), "r"(a[mf][3]),
                      "r"(b[nf][0]), "r"(b[nf][1]));
            }
    }

    if (blockIdx.y == 0) {
#pragma unroll
        for (int mf = 0; mf < 4; mf++) {
            int r0 = rowBase + wm * 64 + mf * 16 + (lane >> 2);
#pragma unroll
            for (int nf = 0; nf < 4; nf++) {
                int col = wn * 32 + nf * 8 + (lane & 3) * 2;
                if (r0 < M) {
                    __nv_bfloat162 p = __floats2bfloat162_rn(acc[mf][nf][0], acc[mf][nf][1]);
                    *(__nv_bfloat162*)(g_Cl + (size_t)r0 * 128 + col) = p;
                }
                if (r0 + 8 < M) {
                    __nv_bfloat162 p = __floats2bfloat162_rn(acc[mf][nf][2], acc[mf][nf][3]);
                    *(__nv_bfloat162*)(g_Cl + (size_t)(r0 + 8) * 128 + col) = p;
                }
            }
        }
    } else {
#pragma unroll
        for (int mf = 0; mf < 4; mf++) {
            int r0 = rowBase + wm * 64 + mf * 16 + (lane >> 2);
#pragma unroll
            for (int nf = 0; nf < 4; nf++) {
                int col = wn * 32 + nf * 8 + (lane & 3) * 2;
                if (r0 < M)
                    *(float2*)(g_Cr + (size_t)r0 * 128 + col) = make_float2(acc[mf][nf][0], acc[mf][nf][1]);
                if (r0 + 8 < M)
                    *(float2*)(g_Cr + (size_t)(r0 + 8) * 128 + col) = make_float2(acc[mf][nf][2], acc[mf][nf][3]);
            }
        }
    }
}

// ---------------- epi1: CSR mean-aggregate + bias + relu, fused layer-2 scalar dots ----------------
// h1 never hits memory: u=h1.w_lu, v=h1.w_lv, p=h1.w_ru, q=h1.w_rv
__global__ void k_epi1(const float* __restrict__ bl) {
    int gw = (blockIdx.x * blockDim.x + threadIdx.x) >> 5;
    int lane = threadIdx.x & 31;
    if (gw >= NN) return;
    int s = g_off[gw], cnt = g_cnt[gw];
    float4 a0 = make_float4(0.f, 0.f, 0.f, 0.f);
    float4 a1 = make_float4(0.f, 0.f, 0.f, 0.f);
    float4 a2 = make_float4(0.f, 0.f, 0.f, 0.f);
    float4 a3 = make_float4(0.f, 0.f, 0.f, 0.f);
    int e = 0;
    for (; e + 4 <= cnt; e += 4) {
        int j0 = g_csr[s + e], j1 = g_csr[s + e + 1], j2 = g_csr[s + e + 2], j3 = g_csr[s + e + 3];
        uint64_t p0 = *(const uint64_t*)(g_Cl + (size_t)j0 * 128 + lane * 4);
        uint64_t p1 = *(const uint64_t*)(g_Cl + (size_t)j1 * 128 + lane * 4);
        uint64_t p2 = *(const uint64_t*)(g_Cl + (size_t)j2 * 128 + lane * 4);
        uint64_t p3 = *(const uint64_t*)(g_Cl + (size_t)j3 * 128 + lane * 4);
        acc_bf16x4(a0, p0); acc_bf16x4(a1, p1); acc_bf16x4(a2, p2); acc_bf16x4(a3, p3);
    }
    for (; e < cnt; e++) {
        int j = g_csr[s + e];
        acc_bf16x4(a0, *(const uint64_t*)(g_Cl + (size_t)j * 128 + lane * 4));
    }
    float inv = 1.0f / (float)max(cnt, 1);
    float4 r = *(const float4*)&g_Cr[(size_t)gw * 128 + lane * 4];
    float4 bb = *(const float4*)&bl[lane * 4];
    float hx = fmaxf((a0.x + a1.x + a2.x + a3.x) * inv + r.x + bb.x, 0.f);
    float hy = fmaxf((a0.y + a1.y + a2.y + a3.y) * inv + r.y + bb.y, 0.f);
    float hz = fmaxf((a0.z + a1.z + a2.z + a3.z) * inv + r.z + bb.z, 0.f);
    float hw = fmaxf((a0.w + a1.w + a2.w + a3.w) * inv + r.w + bb.w, 0.f);

    float4 wlu = *(const float4*)&g_w2[0 * 128 + lane * 4];
    float4 wlv = *(const float4*)&g_w2[1 * 128 + lane * 4];
    float4 wru = *(const float4*)&g_w2[2 * 128 + lane * 4];
    float4 wrv = *(const float4*)&g_w2[3 * 128 + lane * 4];
    float u = hx * wlu.x + hy * wlu.y + hz * wlu.z + hw * wlu.w;
    float v = hx * wlv.x + hy * wlv.y + hz * wlv.z + hw * wlv.w;
    float p = hx * wru.x + hy * wru.y + hz * wru.z + hw * wru.w;
    float q = hx * wrv.x + hy * wrv.y + hz * wrv.z + hw * wrv.w;
#pragma unroll
    for (int d = 16; d > 0; d >>= 1) {
        u += __shfl_xor_sync(0xffffffffu, u, d);
        v += __shfl_xor_sync(0xffffffffu, v, d);
        p += __shfl_xor_sync(0xffffffffu, p, d);
        q += __shfl_xor_sync(0xffffffffu, q, d);
    }
    if (lane == 0) {
        g_uv[gw] = make_float2(u, v);
        g_pq[gw] = make_float2(p, q);
    }
}

// ---------------- epi2: SCALAR CSR aggregation (thread per node) ----------------
__global__ void k_epi2s() {
    int i = blockIdx.x * blockDim.x + threadIdx.x;
    if (i >= NN) return;
    int s = g_off[i], cnt = g_cnt[i];
    float su = 0.f, sv = 0.f;
    for (int e = 0; e < cnt; e++) {
        int j = g_csr[s + e];
        float2 t = g_uv[j];
        su += t.x; sv += t.y;
    }
    float inv = 1.0f / (float)max(cnt, 1);
    float2 pq = g_pq[i];
    g_a[i] = su * inv + pq.x + g_w2c[0];
    g_c[i] = sv * inv + pq.y + g_w2c[1];
}

// ---------------- edge scoring ----------------
__global__ void k_edge(const void* ei, const float* __restrict__ be, float* __restrict__ out) {
    int e = blockIdx.x * blockDim.x + threadIdx.x;
    if (e >= EE) return;
    int s = edge_at(ei, e);
    int t = edge_at(ei, (long)EE + e);
    float z = g_a[s] + g_c[t] + be[0];
    out[e] = 1.f / (1.f + __expf(-z));
}

// ---------------- launcher ----------------
extern "C" void kernel_launch(void* const* d_in, const int* in_sizes, int n_in,
                              void* d_out, int out_size) {
    const float* x   = (const float*)d_in[0];
    const void*  ei  = d_in[1];
    const float* Wl1 = (const float*)d_in[2];
    const float* bl1 = (const float*)d_in[3];
    const float* Wr1 = (const float*)d_in[4];
    const float* Wl2 = (const float*)d_in[5];
    const float* bl2 = (const float*)d_in[6];
    const float* Wr2 = (const float*)d_in[7];
    const float* We  = (const float*)d_in[8];
    const float* be  = (const float*)d_in[9];
    float* out = (float*)d_out;

    const int smemBytes = 2 * 128 * ASTRIDE * (int)sizeof(__nv_bfloat16);
    cudaFuncSetAttribute(k_gemm_mma, cudaFuncAttributeMaxDynamicSharedMemorySize, smemBytes);

    k_prep<<<ZB + PBB + WB, 256>>>(ei, Wl1, Wr1, Wl2, Wr2, bl2, We);
    k_count<<<(EE + 255) / 256, 256>>>(ei);
    k_scan_all<<<1, 1024>>>();
    k_scatter<<<(EE + 255) / 256, 256>>>(ei);

    dim3 gg((NN + 127) / 128, 2);
    k_gemm_mma<<<gg, 256, smemBytes>>>(x, NN);
    k_epi1<<<(NN * 32 + 255) / 256, 256>>>(bl1);
    k_epi2s<<<(NN + 255) / 256, 256>>>();
    k_edge<<<(EE + 255) / 256, 256>>>(ei, be, out);
}

// round 8
// speedup vs baseline: 1.9992x; 1.2516x over previous
#include <cuda_runtime.h>
#include <cuda_bf16.h>
#include <math.h>
#include <stdint.h>

#define NN 50000
#define EE 800000
#define NB 49  // ceil(NN/1024)

// ---------------- device scratch (no allocations allowed) ----------------
__device__ int   g_is64;
__device__ int   g_cnt[NN];
__device__ int   g_off[NN];
__device__ int   g_cur[NN];
__device__ int   g_csr[EE];
__device__ int   g_bsum[NB];
__device__ int   g_src32[EE];
__device__ int   g_tgt32[EE];
__device__ __align__(16) __nv_bfloat16 g_B1b[256 * 128];  // B_ex[n][k] = W1[k][n], [Wl1|Wr1]
__device__ __align__(16) __nv_bfloat16 g_Cl[NN * 128];    // x@Wl1 bf16 (gathered per edge)
__device__ float g_Cr[NN * 128];                          // x@Wr1 fp32 (read once per node)
__device__ __align__(16) float g_w2[4 * 128];  // [Wl2@We0 | Wl2@We1 | Wr2@We0 | Wr2@We1]
__device__ float g_w2c[2];                     // b2.We0, b2.We1
__device__ float2 g_uv[NN];
__device__ float2 g_pq[NN];
__device__ float g_a[NN];
__device__ float g_c[NN];

__device__ __forceinline__ uint32_t smem_u32(const void* p) {
    uint32_t a;
    asm("{ .reg .u64 t; cvta.to.shared.u64 t, %1; cvt.u32.u64 %0, t; }" : "=r"(a) : "l"(p));
    return a;
}

__device__ __forceinline__ void acc_bf16x4(float4& a, uint64_t pk) {
    uint32_t lo = (uint32_t)pk, hi = (uint32_t)(pk >> 32);
    float2 f0 = __bfloat1622float2(*(__nv_bfloat162*)&lo);
    float2 f1 = __bfloat1622float2(*(__nv_bfloat162*)&hi);
    a.x += f0.x; a.y += f0.y; a.z += f1.x; a.w += f1.y;
}

// ---------------- prep: detect + zero cnt + pack W1 (bf16) + fold layer2 weights ----------------
#define ZB ((NN + 255) / 256)
#define PBB ((256 * 128 + 255) / 256)
#define WB 3
__global__ void k_prep(const void* ei,
                       const float* __restrict__ Wl1, const float* __restrict__ Wr1,
                       const float* __restrict__ Wl2, const float* __restrict__ Wr2,
                       const float* __restrict__ bl2, const float* __restrict__ We) {
    int b = blockIdx.x;
    if (b == 0 && threadIdx.x == 0) {
        const int* w = (const int*)ei;
        int all0 = 1;
#pragma unroll
        for (int i = 0; i < 64; i++) all0 &= (w[2 * i + 1] == 0);
        g_is64 = all0;
    }
    if (b < ZB) {
        int i = b * 256 + threadIdx.x;
        if (i < NN) g_cnt[i] = 0;
    } else if (b < ZB + PBB) {
        int i = (b - ZB) * 256 + threadIdx.x;
        int n = i >> 7, k = i & 127;
        float v = (n < 128) ? Wl1[k * 128 + n] : Wr1[k * 128 + (n - 128)];
        g_B1b[i] = __float2bfloat16(v);
    } else {
        int t = (b - ZB - PBB) * 256 + threadIdx.x;
        if (t < 512) {
            int vec = t >> 7;
            int m = t & 127;
            const float* W = (vec < 2) ? Wl2 : Wr2;
            const float* we = We + ((vec & 1) ? 128 : 0);
            float s = 0.f;
#pragma unroll 8
            for (int k = 0; k < 128; k++) s += W[m * 128 + k] * we[k];
            g_w2[vec * 128 + m] = s;
        } else if (t < 514) {
            const float* we = We + ((t - 512) ? 128 : 0);
            float s = 0.f;
#pragma unroll 8
            for (int k = 0; k < 128; k++) s += bl2[k] * we[k];
            g_w2c[t - 512] = s;
        }
    }
}

// ---------------- count + decode edges to int32 (4 edges / thread) ----------------
__global__ void k_count(const void* ei) {
    int base = (blockIdx.x * blockDim.x + threadIdx.x) * 4;
    if (base >= EE) return;
    int is64 = g_is64;
    int s[4], t[4];
    if (is64) {
        const long long* p = (const long long*)ei;
#pragma unroll
        for (int q = 0; q < 4; q++) { s[q] = (int)p[base + q]; t[q] = (int)p[(long)EE + base + q]; }
    } else {
        const int* p = (const int*)ei;
#pragma unroll
        for (int q = 0; q < 4; q++) { s[q] = p[base + q]; t[q] = p[EE + base + q]; }
    }
#pragma unroll
    for (int q = 0; q < 4; q++) {
        g_src32[base + q] = s[q];
        g_tgt32[base + q] = t[q];
        atomicAdd(&g_cnt[t[q]], 1);
    }
}

// ---------------- parallel 2-kernel scan ----------------
__global__ void k_scan1() {
    __shared__ int ws[32];
    int tid = threadIdx.x, lane = tid & 31, w = tid >> 5;
    int i = blockIdx.x * 1024 + tid;
    int v = (i < NN) ? g_cnt[i] : 0;
    int x = v;
#pragma unroll
    for (int d = 1; d < 32; d <<= 1) { int t = __shfl_up_sync(~0u, x, d); if (lane >= d) x += t; }
    if (lane == 31) ws[w] = x;
    __syncthreads();
    if (w == 0) {
        int y = ws[lane];
#pragma unroll
        for (int d = 1; d < 32; d <<= 1) { int t = __shfl_up_sync(~0u, y, d); if (lane >= d) y += t; }
        ws[lane] = y;
    }
    __syncthreads();
    int base = w ? ws[w - 1] : 0;
    int incl = base + x;
    if (i < NN) g_off[i] = incl - v;   // block-local exclusive
    if (tid == 1023) g_bsum[blockIdx.x] = incl;
}

__global__ void k_scan2b() {
    int b = blockIdx.x;
    int base = 0;
    for (int j = 0; j < b; j++) base += g_bsum[j];  // broadcast loads, uniform
    int i = b * 1024 + threadIdx.x;
    if (i < NN) {
        int o = g_off[i] + base;
        g_off[i] = o;
        g_cur[i] = o;
    }
}

// ---------------- scatter (int32, 2 edges / thread) ----------------
__global__ void k_scatter() {
    int base = (blockIdx.x * blockDim.x + threadIdx.x) * 2;
    if (base >= EE) return;
    int s0 = g_src32[base],     t0 = g_tgt32[base];
    int s1 = g_src32[base + 1], t1 = g_tgt32[base + 1];
    int p0 = atomicAdd(&g_cur[t0], 1);
    int p1 = atomicAdd(&g_cur[t1], 1);
    g_csr[p0] = s0;
    g_csr[p1] = s1;
}

// ---------------- HMMA bf16 GEMM (layer 1): single pass, tile[128,256] ----------------
// cols 0:128 -> x@Wl1 -> bf16 g_Cl ; cols 128:256 -> x@Wr1 -> fp32 g_Cr
// 8 warps in 2(M) x 4(N); warp tile 64x64. K=128 staged in smem.
#define ASTRIDE 136
#define SM_GEMM ((128 + 256) * ASTRIDE * 2)  // As 128 rows + Bs 256 rows, bf16

__global__ __launch_bounds__(256) void k_gemm_mma(const float* __restrict__ x, int M) {
    extern __shared__ __nv_bfloat16 sm[];
    __nv_bfloat16* As = sm;                    // [128][ASTRIDE]
    __nv_bfloat16* Bs = sm + 128 * ASTRIDE;    // [256][ASTRIDE]

    const int tid = threadIdx.x;
    const int lane = tid & 31, w = tid >> 5;
    const int rowBase = blockIdx.x * 128;

    // ---- load B: 256 n-rows x 128 k, 1 row/thread ----
    {
        const uint4* src = (const uint4*)(g_B1b + (size_t)tid * 128);
        uint4* dst = (uint4*)(Bs + tid * ASTRIDE);
#pragma unroll
        for (int i = 0; i < 16; i++) dst[i] = src[i];
    }
    // ---- load A: 128 rows x 128 k, fp32 -> bf16, half row/thread ----
    {
        int r = tid >> 1, half = tid & 1;
        int grow = rowBase + r;
        const float4* src = (const float4*)(x + (size_t)grow * 128 + half * 64);
        uint32_t* dst = (uint32_t*)(As + r * ASTRIDE + half * 64);
#pragma unroll
        for (int i = 0; i < 16; i++) {
            float4 v = make_float4(0.f, 0.f, 0.f, 0.f);
            if (grow < M) v = src[i];
            __nv_bfloat162 lo = __floats2bfloat162_rn(v.x, v.y);
            __nv_bfloat162 hi = __floats2bfloat162_rn(v.z, v.w);
            dst[i * 2]     = *(uint32_t*)&lo;
            dst[i * 2 + 1] = *(uint32_t*)&hi;
        }
    }
    __syncthreads();

    const int wm = w >> 2;   // 0..1 (64-row slab)
    const int wn = w & 3;    // 0..3 (64-col slab)

    float acc[4][8][4];
#pragma unroll
    for (int i = 0; i < 4; i++)
#pragma unroll
        for (int j = 0; j < 8; j++)
#pragma unroll
            for (int q = 0; q < 4; q++) acc[i][j][q] = 0.f;

#pragma unroll
    for (int ks = 0; ks < 8; ks++) {
        const int k0 = ks * 16;
        uint32_t a[4][4];
#pragma unroll
        for (int mf = 0; mf < 4; mf++) {
            uint32_t addr = smem_u32(As + (wm * 64 + mf * 16 + (lane & 15)) * ASTRIDE + k0 + (lane >> 4) * 8);
            asm volatile("ldmatrix.sync.aligned.m8n8.x4.shared.b16 {%0,%1,%2,%3}, [%4];"
                         : "=r"(a[mf][0]), "=r"(a[mf][1]), "=r"(a[mf][2]), "=r"(a[mf][3]) : "r"(addr));
        }
        uint32_t b[8][2];
#pragma unroll
        for (int nh = 0; nh < 4; nh++) {
            uint32_t r0, r1, r2, r3;
            uint32_t addr = smem_u32(Bs + (wn * 64 + nh * 16 + (lane & 15)) * ASTRIDE + k0 + (lane >> 4) * 8);
            asm volatile("ldmatrix.sync.aligned.m8n8.x4.shared.b16 {%0,%1,%2,%3}, [%4];"
                         : "=r"(r0), "=r"(r1), "=r"(r2), "=r"(r3) : "r"(addr));
            b[nh * 2 + 0][0] = r0; b[nh * 2 + 0][1] = r2;
            b[nh * 2 + 1][0] = r1; b[nh * 2 + 1][1] = r3;
        }
#pragma unroll
        for (int mf = 0; mf < 4; mf++)
#pragma unroll
            for (int nf = 0; nf < 8; nf++) {
                asm volatile(
                    "mma.sync.aligned.m16n8k16.row.col.f32.bf16.bf16.f32 "
                    "{%0,%1,%2,%3}, {%4,%5,%6,%7}, {%8,%9}, {%0,%1,%2,%3};"
                    : "+f"(acc[mf][nf][0]), "+f"(acc[mf][nf][1]), "+f"(acc[mf][nf][2]), "+f"(acc[mf][nf][3])
                    : "r"(a[mf][0]), "r"(a[mf][1]), "r"(a[mf][2]), "r"(a[mf][3]),
                      "r"(b[nf][0]), "r"(b[nf][1]));
            }
    }

    // ---- epilogue: wn 0,1 -> g_Cl (bf16); wn 2,3 -> g_Cr (fp32) ----
#pragma unroll
    for (int mf = 0; mf < 4; mf++) {
        int r0 = rowBase + wm * 64 + mf * 16 + (lane >> 2);
#pragma unroll
        for (int nf = 0; nf < 8; nf++) {
            int col = wn * 64 + nf * 8 + (lane & 3) * 2;   // 0..255
            if (col < 128) {
                if (r0 < M) {
                    __nv_bfloat162 p = __floats2bfloat162_rn(acc[mf][nf][0], acc[mf][nf][1]);
                    *(__nv_bfloat162*)(g_Cl + (size_t)r0 * 128 + col) = p;
                }
                if (r0 + 8 < M) {
                    __nv_bfloat162 p = __floats2bfloat162_rn(acc[mf][nf][2], acc[mf][nf][3]);
                    *(__nv_bfloat162*)(g_Cl + (size_t)(r0 + 8) * 128 + col) = p;
                }
            } else {
                int c = col - 128;
                if (r0 < M)
                    *(float2*)(g_Cr + (size_t)r0 * 128 + c) = make_float2(acc[mf][nf][0], acc[mf][nf][1]);
                if (r0 + 8 < M)
                    *(float2*)(g_Cr + (size_t)(r0 + 8) * 128 + c) = make_float2(acc[mf][nf][2], acc[mf][nf][3]);
            }
        }
    }
}

// ---------------- epi1: CSR mean-aggregate + bias + relu, fused layer-2 scalar dots ----------------
__global__ void k_epi1(const float* __restrict__ bl) {
    int gw = (blockIdx.x * blockDim.x + threadIdx.x) >> 5;
    int lane = threadIdx.x & 31;
    if (gw >= NN) return;
    int s = g_off[gw], cnt = g_cnt[gw];
    float4 a0 = make_float4(0.f, 0.f, 0.f, 0.f);
    float4 a1 = make_float4(0.f, 0.f, 0.f, 0.f);
    float4 a2 = make_float4(0.f, 0.f, 0.f, 0.f);
    float4 a3 = make_float4(0.f, 0.f, 0.f, 0.f);
    int e = 0;
    for (; e + 4 <= cnt; e += 4) {
        int j0 = g_csr[s + e], j1 = g_csr[s + e + 1], j2 = g_csr[s + e + 2], j3 = g_csr[s + e + 3];
        uint64_t p0 = *(const uint64_t*)(g_Cl + (size_t)j0 * 128 + lane * 4);
        uint64_t p1 = *(const uint64_t*)(g_Cl + (size_t)j1 * 128 + lane * 4);
        uint64_t p2 = *(const uint64_t*)(g_Cl + (size_t)j2 * 128 + lane * 4);
        uint64_t p3 = *(const uint64_t*)(g_Cl + (size_t)j3 * 128 + lane * 4);
        acc_bf16x4(a0, p0); acc_bf16x4(a1, p1); acc_bf16x4(a2, p2); acc_bf16x4(a3, p3);
    }
    for (; e < cnt; e++) {
        int j = g_csr[s + e];
        acc_bf16x4(a0, *(const uint64_t*)(g_Cl + (size_t)j * 128 + lane * 4));
    }
    float inv = 1.0f / (float)max(cnt, 1);
    float4 r = *(const float4*)&g_Cr[(size_t)gw * 128 + lane * 4];
    float4 bb = *(const float4*)&bl[lane * 4];
    float hx = fmaxf((a0.x + a1.x + a2.x + a3.x) * inv + r.x + bb.x, 0.f);
    float hy = fmaxf((a0.y + a1.y + a2.y + a3.y) * inv + r.y + bb.y, 0.f);
    float hz = fmaxf((a0.z + a1.z + a2.z + a3.z) * inv + r.z + bb.z, 0.f);
    float hw = fmaxf((a0.w + a1.w + a2.w + a3.w) * inv + r.w + bb.w, 0.f);

    float4 wlu = *(const float4*)&g_w2[0 * 128 + lane * 4];
    float4 wlv = *(const float4*)&g_w2[1 * 128 + lane * 4];
    float4 wru = *(const float4*)&g_w2[2 * 128 + lane * 4];
    float4 wrv = *(const float4*)&g_w2[3 * 128 + lane * 4];
    float u = hx * wlu.x + hy * wlu.y + hz * wlu.z + hw * wlu.w;
    float v = hx * wlv.x + hy * wlv.y + hz * wlv.z + hw * wlv.w;
    float p = hx * wru.x + hy * wru.y + hz * wru.z + hw * wru.w;
    float q = hx * wrv.x + hy * wrv.y + hz * wrv.z + hw * wrv.w;
#pragma unroll
    for (int d = 16; d > 0; d >>= 1) {
        u += __shfl_xor_sync(0xffffffffu, u, d);
        v += __shfl_xor_sync(0xffffffffu, v, d);
        p += __shfl_xor_sync(0xffffffffu, p, d);
        q += __shfl_xor_sync(0xffffffffu, q, d);
    }
    if (lane == 0) {
        g_uv[gw] = make_float2(u, v);
        g_pq[gw] = make_float2(p, q);
    }
}

// ---------------- epi2: scalar CSR aggregation (thread per node, unroll 4) ----------------
__global__ void k_epi2s() {
    int i = blockIdx.x * blockDim.x + threadIdx.x;
    if (i >= NN) return;
    int s = g_off[i], cnt = g_cnt[i];
    float su = 0.f, sv = 0.f;
    int e = 0;
    for (; e + 4 <= cnt; e += 4) {
        int j0 = g_csr[s + e], j1 = g_csr[s + e + 1], j2 = g_csr[s + e + 2], j3 = g_csr[s + e + 3];
        float2 t0 = g_uv[j0], t1 = g_uv[j1], t2 = g_uv[j2], t3 = g_uv[j3];
        su += t0.x + t1.x + t2.x + t3.x;
        sv += t0.y + t1.y + t2.y + t3.y;
    }
    for (; e < cnt; e++) {
        float2 t = g_uv[g_csr[s + e]];
        su += t.x; sv += t.y;
    }
    float inv = 1.0f / (float)max(cnt, 1);
    float2 pq = g_pq[i];
    g_a[i] = su * inv + pq.x + g_w2c[0];
    g_c[i] = sv * inv + pq.y + g_w2c[1];
}

// ---------------- edge scoring (int32 decoded) ----------------
__global__ void k_edge(const float* __restrict__ be, float* __restrict__ out) {
    int e = blockIdx.x * blockDim.x + threadIdx.x;
    if (e >= EE) return;
    int s = g_src32[e];
    int t = g_tgt32[e];
    float z = g_a[s] + g_c[t] + be[0];
    out[e] = 1.f / (1.f + __expf(-z));
}

// ---------------- launcher ----------------
extern "C" void kernel_launch(void* const* d_in, const int* in_sizes, int n_in,
                              void* d_out, int out_size) {
    const float* x   = (const float*)d_in[0];
    const void*  ei  = d_in[1];
    const float* Wl1 = (const float*)d_in[2];
    const float* bl1 = (const float*)d_in[3];
    const float* Wr1 = (const float*)d_in[4];
    const float* Wl2 = (const float*)d_in[5];
    const float* bl2 = (const float*)d_in[6];
    const float* Wr2 = (const float*)d_in[7];
    const float* We  = (const float*)d_in[8];
    const float* be  = (const float*)d_in[9];
    float* out = (float*)d_out;

    cudaFuncSetAttribute(k_gemm_mma, cudaFuncAttributeMaxDynamicSharedMemorySize, SM_GEMM);

    k_prep<<<ZB + PBB + WB, 256>>>(ei, Wl1, Wr1, Wl2, Wr2, bl2, We);
    k_count<<<(EE / 4 + 255) / 256, 256>>>(ei);
    k_scan1<<<NB, 1024>>>();
    k_scan2b<<<NB, 1024>>>();
    k_scatter<<<(EE / 2 + 255) / 256, 256>>>();

    k_gemm_mma<<<(NN + 127) / 128, 256, SM_GEMM>>>(x, NN);
    k_epi1<<<(NN * 32 + 255) / 256, 256>>>(bl1);
    k_epi2s<<<(NN + 255) / 256, 256>>>();
    k_edge<<<(EE + 255) / 256, 256>>>(be, out);
}

// round 9
// speedup vs baseline: 2.0103x; 1.0055x over previous
#include <cuda_runtime.h>
#include <cuda_bf16.h>
#include <math.h>
#include <stdint.h>

#define NN 50000
#define EE 800000
#define NB 49  // ceil(NN/1024)

// ---------------- device scratch (no allocations allowed) ----------------
__device__ int   g_is64;
__device__ int   g_cnt[NN];
__device__ int   g_off[NN];
__device__ int   g_cur[NN];
__device__ int   g_csr[EE];
__device__ int   g_bsum[NB];
__device__ int   g_src32[EE];
__device__ int   g_tgt32[EE];
__device__ __align__(16) __nv_bfloat16 g_B1b[256 * 128];  // B_ex[n][k] = W1[k][n], [Wl1|Wr1]
__device__ __align__(16) __nv_bfloat16 g_Cl[NN * 128];    // x@Wl1 bf16 (gathered per edge)
__device__ float g_Cr[NN * 128];                          // x@Wr1 fp32 (read once per node)
__device__ __align__(16) float g_w2[4 * 128];  // [Wl2@We0 | Wl2@We1 | Wr2@We0 | Wr2@We1]
__device__ float g_w2c[2];                     // b2.We0, b2.We1
__device__ float2 g_uv[NN];
__device__ float2 g_pq[NN];
__device__ float g_a[NN];
__device__ float g_c[NN];

__device__ __forceinline__ uint32_t smem_u32(const void* p) {
    uint32_t a;
    asm("{ .reg .u64 t; cvta.to.shared.u64 t, %1; cvt.u32.u64 %0, t; }" : "=r"(a) : "l"(p));
    return a;
}

__device__ __forceinline__ void acc_bf16x4(float4& a, uint64_t pk) {
    uint32_t lo = (uint32_t)pk, hi = (uint32_t)(pk >> 32);
    float2 f0 = __bfloat1622float2(*(__nv_bfloat162*)&lo);
    float2 f1 = __bfloat1622float2(*(__nv_bfloat162*)&hi);
    a.x += f0.x; a.y += f0.y; a.z += f1.x; a.w += f1.y;
}

// ---------------- prep: detect + zero cnt + pack W1 (bf16) + fold layer2 weights ----------------
#define ZB ((NN + 255) / 256)
#define PBB ((256 * 128 + 255) / 256)
#define WB 3
__global__ void k_prep(const void* ei,
                       const float* __restrict__ Wl1, const float* __restrict__ Wr1,
                       const float* __restrict__ Wl2, const float* __restrict__ Wr2,
                       const float* __restrict__ bl2, const float* __restrict__ We) {
    int b = blockIdx.x;
    if (b == 0 && threadIdx.x == 0) {
        const int* w = (const int*)ei;
        int all0 = 1;
#pragma unroll
        for (int i = 0; i < 64; i++) all0 &= (w[2 * i + 1] == 0);
        g_is64 = all0;
    }
    if (b < ZB) {
        int i = b * 256 + threadIdx.x;
        if (i < NN) g_cnt[i] = 0;
    } else if (b < ZB + PBB) {
        int i = (b - ZB) * 256 + threadIdx.x;
        int n = i >> 7, k = i & 127;
        float v = (n < 128) ? Wl1[k * 128 + n] : Wr1[k * 128 + (n - 128)];
        g_B1b[i] = __float2bfloat16(v);
    } else {
        int t = (b - ZB - PBB) * 256 + threadIdx.x;
        if (t < 512) {
            int vec = t >> 7;
            int m = t & 127;
            const float* W = (vec < 2) ? Wl2 : Wr2;
            const float* we = We + ((vec & 1) ? 128 : 0);
            float s = 0.f;
#pragma unroll 8
            for (int k = 0; k < 128; k++) s += W[m * 128 + k] * we[k];
            g_w2[vec * 128 + m] = s;
        } else if (t < 514) {
            const float* we = We + ((t - 512) ? 128 : 0);
            float s = 0.f;
#pragma unroll 8
            for (int k = 0; k < 128; k++) s += bl2[k] * we[k];
            g_w2c[t - 512] = s;
        }
    }
}

// ---------------- count + decode edges to int32 (4 edges / thread) ----------------
__global__ void k_count(const void* ei) {
    int base = (blockIdx.x * blockDim.x + threadIdx.x) * 4;
    if (base >= EE) return;
    int is64 = g_is64;
    int s[4], t[4];
    if (is64) {
        const long long* p = (const long long*)ei;
#pragma unroll
        for (int q = 0; q < 4; q++) { s[q] = (int)p[base + q]; t[q] = (int)p[(long)EE + base + q]; }
    } else {
        const int* p = (const int*)ei;
#pragma unroll
        for (int q = 0; q < 4; q++) { s[q] = p[base + q]; t[q] = p[EE + base + q]; }
    }
#pragma unroll
    for (int q = 0; q < 4; q++) {
        g_src32[base + q] = s[q];
        g_tgt32[base + q] = t[q];
        atomicAdd(&g_cnt[t[q]], 1);
    }
}

// ---------------- parallel 2-kernel scan ----------------
__global__ void k_scan1() {
    __shared__ int ws[32];
    int tid = threadIdx.x, lane = tid & 31, w = tid >> 5;
    int i = blockIdx.x * 1024 + tid;
    int v = (i < NN) ? g_cnt[i] : 0;
    int x = v;
#pragma unroll
    for (int d = 1; d < 32; d <<= 1) { int t = __shfl_up_sync(~0u, x, d); if (lane >= d) x += t; }
    if (lane == 31) ws[w] = x;
    __syncthreads();
    if (w == 0) {
        int y = ws[lane];
#pragma unroll
        for (int d = 1; d < 32; d <<= 1) { int t = __shfl_up_sync(~0u, y, d); if (lane >= d) y += t; }
        ws[lane] = y;
    }
    __syncthreads();
    int base = w ? ws[w - 1] : 0;
    int incl = base + x;
    if (i < NN) g_off[i] = incl - v;   // block-local exclusive
    if (tid == 1023) g_bsum[blockIdx.x] = incl;
}

// base for block b = sum of bsum[0..b-1], via one-warp masked reduction (2 loads/lane)
__global__ void k_scan2b() {
    __shared__ int base_sh;
    int b = blockIdx.x, tid = threadIdx.x, lane = tid & 31, w = tid >> 5;
    if (w == 0) {
        int s = 0;
        if (lane < b && lane < NB) s += g_bsum[lane];
        int l2 = lane + 32;
        if (l2 < b && l2 < NB) s += g_bsum[l2];
#pragma unroll
        for (int d = 16; d > 0; d >>= 1) s += __shfl_xor_sync(~0u, s, d);
        if (lane == 0) base_sh = s;
    }
    __syncthreads();
    int base = base_sh;
    int i = b * 1024 + tid;
    if (i < NN) {
        int o = g_off[i] + base;
        g_off[i] = o;
        g_cur[i] = o;
    }
}

// ---------------- scatter (int32, 2 edges / thread) ----------------
__global__ void k_scatter() {
    int base = (blockIdx.x * blockDim.x + threadIdx.x) * 2;
    if (base >= EE) return;
    int s0 = g_src32[base],     t0 = g_tgt32[base];
    int s1 = g_src32[base + 1], t1 = g_tgt32[base + 1];
    int p0 = atomicAdd(&g_cur[t0], 1);
    int p1 = atomicAdd(&g_cur[t1], 1);
    g_csr[p0] = s0;
    g_csr[p1] = s1;
}

// ---------------- HMMA bf16 GEMM (layer 1): single pass, tile[128,256] ----------------
#define ASTRIDE 136
#define SM_GEMM ((128 + 256) * ASTRIDE * 2)

__global__ __launch_bounds__(256) void k_gemm_mma(const float* __restrict__ x, int M) {
    extern __shared__ __nv_bfloat16 sm[];
    __nv_bfloat16* As = sm;                    // [128][ASTRIDE]
    __nv_bfloat16* Bs = sm + 128 * ASTRIDE;    // [256][ASTRIDE]

    const int tid = threadIdx.x;
    const int lane = tid & 31, w = tid >> 5;
    const int rowBase = blockIdx.x * 128;

    {
        const uint4* src = (const uint4*)(g_B1b + (size_t)tid * 128);
        uint4* dst = (uint4*)(Bs + tid * ASTRIDE);
#pragma unroll
        for (int i = 0; i < 16; i++) dst[i] = src[i];
    }
    {
        int r = tid >> 1, half = tid & 1;
        int grow = rowBase + r;
        const float4* src = (const float4*)(x + (size_t)grow * 128 + half * 64);
        uint32_t* dst = (uint32_t*)(As + r * ASTRIDE + half * 64);
#pragma unroll
        for (int i = 0; i < 16; i++) {
            float4 v = make_float4(0.f, 0.f, 0.f, 0.f);
            if (grow < M) v = src[i];
            __nv_bfloat162 lo = __floats2bfloat162_rn(v.x, v.y);
            __nv_bfloat162 hi = __floats2bfloat162_rn(v.z, v.w);
            dst[i * 2]     = *(uint32_t*)&lo;
            dst[i * 2 + 1] = *(uint32_t*)&hi;
        }
    }
    __syncthreads();

    const int wm = w >> 2;
    const int wn = w & 3;

    float acc[4][8][4];
#pragma unroll
    for (int i = 0; i < 4; i++)
#pragma unroll
        for (int j = 0; j < 8; j++)
#pragma unroll
            for (int q = 0; q < 4; q++) acc[i][j][q] = 0.f;

#pragma unroll
    for (int ks = 0; ks < 8; ks++) {
        const int k0 = ks * 16;
        uint32_t a[4][4];
#pragma unroll
        for (int mf = 0; mf < 4; mf++) {
            uint32_t addr = smem_u32(As + (wm * 64 + mf * 16 + (lane & 15)) * ASTRIDE + k0 + (lane >> 4) * 8);
            asm volatile("ldmatrix.sync.aligned.m8n8.x4.shared.b16 {%0,%1,%2,%3}, [%4];"
                         : "=r"(a[mf][0]), "=r"(a[mf][1]), "=r"(a[mf][2]), "=r"(a[mf][3]) : "r"(addr));
        }
        uint32_t b[8][2];
#pragma unroll
        for (int nh = 0; nh < 4; nh++) {
            uint32_t r0, r1, r2, r3;
            uint32_t addr = smem_u32(Bs + (wn * 64 + nh * 16 + (lane & 15)) * ASTRIDE + k0 + (lane >> 4) * 8);
            asm volatile("ldmatrix.sync.aligned.m8n8.x4.shared.b16 {%0,%1,%2,%3}, [%4];"
                         : "=r"(r0), "=r"(r1), "=r"(r2), "=r"(r3) : "r"(addr));
            b[nh * 2 + 0][0] = r0; b[nh * 2 + 0][1] = r2;
            b[nh * 2 + 1][0] = r1; b[nh * 2 + 1][1] = r3;
        }
#pragma unroll
        for (int mf = 0; mf < 4; mf++)
#pragma unroll
            for (int nf = 0; nf < 8; nf++) {
                asm volatile(
                    "mma.sync.aligned.m16n8k16.row.col.f32.bf16.bf16.f32 "
                    "{%0,%1,%2,%3}, {%4,%5,%6,%7}, {%8,%9}, {%0,%1,%2,%3};"
                    : "+f"(acc[mf][nf][0]), "+f"(acc[mf][nf][1]), "+f"(acc[mf][nf][2]), "+f"(acc[mf][nf][3])
                    : "r"(a[mf][0]), "r"(a[mf][1]), "r"(a[mf][2]), "r"(a[mf][3]),
                      "r"(b[nf][0]), "r"(b[nf][1]));
            }
    }

#pragma unroll
    for (int mf = 0; mf < 4; mf++) {
        int r0 = rowBase + wm * 64 + mf * 16 + (lane >> 2);
#pragma unroll
        for (int nf = 0; nf < 8; nf++) {
            int col = wn * 64 + nf * 8 + (lane & 3) * 2;
            if (col < 128) {
                if (r0 < M) {
                    __nv_bfloat162 p = __floats2bfloat162_rn(acc[mf][nf][0], acc[mf][nf][1]);
                    *(__nv_bfloat162*)(g_Cl + (size_t)r0 * 128 + col) = p;
                }
                if (r0 + 8 < M) {
                    __nv_bfloat162 p = __floats2bfloat162_rn(acc[mf][nf][2], acc[mf][nf][3]);
                    *(__nv_bfloat162*)(g_Cl + (size_t)(r0 + 8) * 128 + col) = p;
                }
            } else {
                int c = col - 128;
                if (r0 < M)
                    *(float2*)(g_Cr + (size_t)r0 * 128 + c) = make_float2(acc[mf][nf][0], acc[mf][nf][1]);
                if (r0 + 8 < M)
                    *(float2*)(g_Cr + (size_t)(r0 + 8) * 128 + c) = make_float2(acc[mf][nf][2], acc[mf][nf][3]);
            }
        }
    }
}

// ---------------- epi1: CSR mean-aggregate + bias + relu, fused layer-2 scalar dots ----------------
__global__ void k_epi1(const float* __restrict__ bl) {
    int gw = (blockIdx.x * blockDim.x + threadIdx.x) >> 5;
    int lane = threadIdx.x & 31;
    if (gw >= NN) return;
    int s = g_off[gw], cnt = g_cnt[gw];
    float4 a0 = make_float4(0.f, 0.f, 0.f, 0.f);
    float4 a1 = make_float4(0.f, 0.f, 0.f, 0.f);
    float4 a2 = make_float4(0.f, 0.f, 0.f, 0.f);
    float4 a3 = make_float4(0.f, 0.f, 0.f, 0.f);
    int e = 0;
    for (; e + 4 <= cnt; e += 4) {
        int j0 = g_csr[s + e], j1 = g_csr[s + e + 1], j2 = g_csr[s + e + 2], j3 = g_csr[s + e + 3];
        uint64_t p0 = *(const uint64_t*)(g_Cl + (size_t)j0 * 128 + lane * 4);
        uint64_t p1 = *(const uint64_t*)(g_Cl + (size_t)j1 * 128 + lane * 4);
        uint64_t p2 = *(const uint64_t*)(g_Cl + (size_t)j2 * 128 + lane * 4);
        uint64_t p3 = *(const uint64_t*)(g_Cl + (size_t)j3 * 128 + lane * 4);
        acc_bf16x4(a0, p0); acc_bf16x4(a1, p1); acc_bf16x4(a2, p2); acc_bf16x4(a3, p3);
    }
    for (; e < cnt; e++) {
        int j = g_csr[s + e];
        acc_bf16x4(a0, *(const uint64_t*)(g_Cl + (size_t)j * 128 + lane * 4));
    }
    float inv = 1.0f / (float)max(cnt, 1);
    float4 r = *(const float4*)&g_Cr[(size_t)gw * 128 + lane * 4];
    float4 bb = *(const float4*)&bl[lane * 4];
    float hx = fmaxf((a0.x + a1.x + a2.x + a3.x) * inv + r.x + bb.x, 0.f);
    float hy = fmaxf((a0.y + a1.y + a2.y + a3.y) * inv + r.y + bb.y, 0.f);
    float hz = fmaxf((a0.z + a1.z + a2.z + a3.z) * inv + r.z + bb.z, 0.f);
    float hw = fmaxf((a0.w + a1.w + a2.w + a3.w) * inv + r.w + bb.w, 0.f);

    float4 wlu = *(const float4*)&g_w2[0 * 128 + lane * 4];
    float4 wlv = *(const float4*)&g_w2[1 * 128 + lane * 4];
    float4 wru = *(const float4*)&g_w2[2 * 128 + lane * 4];
    float4 wrv = *(const float4*)&g_w2[3 * 128 + lane * 4];
    float u = hx * wlu.x + hy * wlu.y + hz * wlu.z + hw * wlu.w;
    float v = hx * wlv.x + hy * wlv.y + hz * wlv.z + hw * wlv.w;
    float p = hx * wru.x + hy * wru.y + hz * wru.z + hw * wru.w;
    float q = hx * wrv.x + hy * wrv.y + hz * wrv.z + hw * wrv.w;
#pragma unroll
    for (int d = 16; d > 0; d >>= 1) {
        u += __shfl_xor_sync(0xffffffffu, u, d);
        v += __shfl_xor_sync(0xffffffffu, v, d);
        p += __shfl_xor_sync(0xffffffffu, p, d);
        q += __shfl_xor_sync(0xffffffffu, q, d);
    }
    if (lane == 0) {
        g_uv[gw] = make_float2(u, v);
        g_pq[gw] = make_float2(p, q);
    }
}

// ---------------- epi2: scalar CSR aggregation ----------------
__global__ void k_epi2s() {
    int i = blockIdx.x * blockDim.x + threadIdx.x;
    if (i >= NN) return;
    int s = g_off[i], cnt = g_cnt[i];
    float su = 0.f, sv = 0.f;
    int e = 0;
    for (; e + 4 <= cnt; e += 4) {
        int j0 = g_csr[s + e], j1 = g_csr[s + e + 1], j2 = g_csr[s + e + 2], j3 = g_csr[s + e + 3];
        float2 t0 = g_uv[j0], t1 = g_uv[j1], t2 = g_uv[j2], t3 = g_uv[j3];
        su += t0.x + t1.x + t2.x + t3.x;
        sv += t0.y + t1.y + t2.y + t3.y;
    }
    for (; e < cnt; e++) {
        float2 t = g_uv[g_csr[s + e]];
        su += t.x; sv += t.y;
    }
    float inv = 1.0f / (float)max(cnt, 1);
    float2 pq = g_pq[i];
    g_a[i] = su * inv + pq.x + g_w2c[0];
    g_c[i] = sv * inv + pq.y + g_w2c[1];
}

// ---------------- edge scoring ----------------
__global__ void k_edge(const float* __restrict__ be, float* __restrict__ out) {
    int e = blockIdx.x * blockDim.x + threadIdx.x;
    if (e >= EE) return;
    int s = g_src32[e];
    int t = g_tgt32[e];
    float z = g_a[s] + g_c[t] + be[0];
    out[e] = 1.f / (1.f + __expf(-z));
}

// ---------------- launcher: fork GEMM onto per-thread stream, join before epi1 ----------------
extern "C" void kernel_launch(void* const* d_in, const int* in_sizes, int n_in,
                              void* d_out, int out_size) {
    const float* x   = (const float*)d_in[0];
    const void*  ei  = d_in[1];
    const float* Wl1 = (const float*)d_in[2];
    const float* bl1 = (const float*)d_in[3];
    const float* Wr1 = (const float*)d_in[4];
    const float* Wl2 = (const float*)d_in[5];
    const float* bl2 = (const float*)d_in[6];
    const float* Wr2 = (const float*)d_in[7];
    const float* We  = (const float*)d_in[8];
    const float* be  = (const float*)d_in[9];
    float* out = (float*)d_out;

    cudaFuncSetAttribute(k_gemm_mma, cudaFuncAttributeMaxDynamicSharedMemorySize, SM_GEMM);

    // events: created per call, intentionally not destroyed (destroying a captured
    // event during active capture is illegal; only the few setup calls leak them,
    // graph replays don't re-run this function). Host-side objects only.
    cudaEvent_t evFork, evJoin;
    cudaEventCreateWithFlags(&evFork, cudaEventDisableTiming);
    cudaEventCreateWithFlags(&evJoin, cudaEventDisableTiming);

    k_prep<<<ZB + PBB + WB, 256>>>(ei, Wl1, Wr1, Wl2, Wr2, bl2, We);

    // fork: GEMM depends only on prep (B1b pack) + x
    cudaEventRecord(evFork, 0);
    cudaStreamWaitEvent(cudaStreamPerThread, evFork, 0);
    k_gemm_mma<<<(NN + 127) / 128, 256, SM_GEMM, cudaStreamPerThread>>>(x, NN);
    cudaEventRecord(evJoin, cudaStreamPerThread);

    // graph-build branch on legacy stream
    k_count<<<(EE / 4 + 255) / 256, 256>>>(ei);
    k_scan1<<<NB, 1024>>>();
    k_scan2b<<<NB, 1024>>>();
    k_scatter<<<(EE / 2 + 255) / 256, 256>>>();

    // join: epi1 needs both GEMM output and CSR
    cudaStreamWaitEvent(0, evJoin, 0);
    k_epi1<<<(NN * 32 + 255) / 256, 256>>>(bl1);
    k_epi2s<<<(NN + 255) / 256, 256>>>();
    k_edge<<<(EE + 255) / 256, 256>>>(be, out);
}